// round 10
// baseline (speedup 1.0000x reference)
#include <cuda_runtime.h>
#include <math.h>

// ---------------------------------------------------------------------------
// TensoRF shading, round 2: packed-f32x2 (FFMA2) MLP + sincos double-angle
// recurrence. Per block: 32 samples. Encoded input stored TRANSPOSED in SMEM
// (row = channel, col = sample) with a pair-swizzle so that:
//   - GEMM reads are LDS.64 broadcasts (all lanes of a warp share a sample grp)
//   - epilogue STS.64 writes land exactly 2 lanes per bank-pair (free)
// Thread tile: 4 output features x 4 samples = 8 f32x2 accumulators.
// ---------------------------------------------------------------------------

#define NRAYS 4096
#define NS    128
#define NSAMP (NRAYS * NS)
#define APPD  27
#define INC   390
#define FC    128
#define STILE 32
#define THREADS 256

// col slot for (row r, sample s) in a transposed 32-wide tile
#define XCOL(r, s) ((((((s) >> 1) + ((r) >> 2)) & 15) << 1) + ((s) & 1))

static __device__ float g_rgb[(size_t)NSAMP * 3];

__device__ __forceinline__ unsigned long long pk2(float a, float b) {
    unsigned long long r;
    asm("mov.b64 %0, {%1, %2};" : "=l"(r)
        : "r"(__float_as_uint(a)), "r"(__float_as_uint(b)));
    return r;
}
__device__ __forceinline__ void upk2(unsigned long long p, float& a, float& b) {
    unsigned int x, y;
    asm("mov.b64 {%0, %1}, %2;" : "=r"(x), "=r"(y) : "l"(p));
    a = __uint_as_float(x); b = __uint_as_float(y);
}
__device__ __forceinline__ unsigned long long ffma2(
    unsigned long long a, unsigned long long b, unsigned long long c) {
    unsigned long long d;
    asm("fma.rn.f32x2 %0, %1, %2, %3;" : "=l"(d) : "l"(a), "l"(b), "l"(c));
    return d;
}

// one 4-column step of the register-tiled GEMM
__device__ __forceinline__ void gemm_step(
    const float* __restrict__ xs, const float4* __restrict__ wp,
    int c, int colA, int colB,
    unsigned long long a01[4], unsigned long long a23[4])
{
    unsigned long long x01 = *(const unsigned long long*)(xs + c * 32 + colA);
    unsigned long long x23 = *(const unsigned long long*)(xs + c * 32 + colB);
    float4 w = wp[c * 32];
    unsigned long long w0 = pk2(w.x, w.x);
    unsigned long long w1 = pk2(w.y, w.y);
    unsigned long long w2 = pk2(w.z, w.z);
    unsigned long long w3 = pk2(w.w, w.w);
    a01[0] = ffma2(x01, w0, a01[0]);  a23[0] = ffma2(x23, w0, a23[0]);
    a01[1] = ffma2(x01, w1, a01[1]);  a23[1] = ffma2(x23, w1, a23[1]);
    a01[2] = ffma2(x01, w2, a01[2]);  a23[2] = ffma2(x23, w2, a23[2]);
    a01[3] = ffma2(x01, w3, a01[3]);  a23[3] = ffma2(x23, w3, a23[3]);
}

__device__ __forceinline__ void gemm_epilogue(
    float* __restrict__ dst, const float* __restrict__ bias,
    int fg, int sh,
    unsigned long long a01[4], unsigned long long a23[4])
{
    const float4 bb = *((const float4*)bias + fg);
    const float bf[4] = {bb.x, bb.y, bb.z, bb.w};
    const int colAw = ((sh + fg) & 15) << 1;
    const int colBw = ((sh + 1 + fg) & 15) << 1;
    #pragma unroll
    for (int f = 0; f < 4; f++) {
        int r = 4 * fg + f;
        float v0, v1, v2, v3;
        upk2(a01[f], v0, v1);
        upk2(a23[f], v2, v3);
        v0 = fmaxf(v0 + bf[f], 0.f);
        v1 = fmaxf(v1 + bf[f], 0.f);
        v2 = fmaxf(v2 + bf[f], 0.f);
        v3 = fmaxf(v3 + bf[f], 0.f);
        *(unsigned long long*)(dst + r * 32 + colAw) = pk2(v0, v1);
        *(unsigned long long*)(dst + r * 32 + colBw) = pk2(v2, v3);
    }
}

__global__ void __launch_bounds__(THREADS) mlp_kernel(
    const float* __restrict__ app,
    const float* __restrict__ view,
    const float* __restrict__ W1, const float* __restrict__ b1,
    const float* __restrict__ W2, const float* __restrict__ b2,
    const float* __restrict__ W3, const float* __restrict__ b3)
{
    extern __shared__ __align__(16) float smem[];
    float* xs  = smem;            // [392][32] encoded input (transposed), 390 rows used
    float* h1  = xs + 392 * 32;   // [128][32]
    float* h2  = h1 + 128 * 32;   // [128][32]
    float* w3s = h2 + 128 * 32;   // [384]
    float* b3s = w3s + 384;       // [4]

    const int tid = threadIdx.x;
    const size_t base = (size_t)blockIdx.x * STILE;

    // ---- stage W3/b3 ----
    w3s[tid] = W3[tid & 255 ? tid : tid];  // plain copy below
    w3s[tid] = W3[tid];
    if (tid < 128) w3s[256 + tid] = W3[256 + tid];
    if (tid < 3)   b3s[tid] = b3[tid];

    // ---- build encoded input (transposed, pair-swizzled) ----
    // rows: [0:27) app | [27:30) view | [30:192) sin(PE app) | [192:354) cos
    //       | [354:372) sin(PE view) | [372:390) cos(PE view)
    {
        const int s = tid >> 3;   // 0..31
        const int j = tid & 7;
        const size_t gs = base + s;
        const float* af = app + gs * APPD;
        #pragma unroll
        for (int cc = 0; cc < 4; cc++) {
            int c = j + cc * 8;
            if (c < APPD) {
                float v = af[c];
                xs[c * 32 + XCOL(c, s)] = v;
                float sn, cs;
                __sincosf(v, &sn, &cs);
                int rs = 30 + c * 6, rc = 192 + c * 6;
                #pragma unroll
                for (int f = 0; f < 6; f++) {
                    xs[(rs + f) * 32 + XCOL(rs + f, s)] = sn;
                    xs[(rc + f) * 32 + XCOL(rc + f, s)] = cs;
                    float sn2 = 2.f * sn * cs;        // double-angle recurrence
                    float cs2 = 1.f - 2.f * sn * sn;
                    sn = sn2; cs = cs2;
                }
            }
        }
        if (j < 3) {
            float v = view[gs * 3 + j];
            xs[(27 + j) * 32 + XCOL(27 + j, s)] = v;
            float sn, cs;
            __sincosf(v, &sn, &cs);
            int rs = 354 + j * 6, rc = 372 + j * 6;
            #pragma unroll
            for (int f = 0; f < 6; f++) {
                xs[(rs + f) * 32 + XCOL(rs + f, s)] = sn;
                xs[(rc + f) * 32 + XCOL(rc + f, s)] = cs;
                float sn2 = 2.f * sn * cs;
                float cs2 = 1.f - 2.f * sn * sn;
                sn = sn2; cs = cs2;
            }
        }
    }
    __syncthreads();

    const int fg = tid & 31;        // feature group: outputs 4fg..4fg+3
    const int sg = tid >> 5;        // sample group (warp): samples 4sg..4sg+3
    const int s0 = 4 * sg;
    const int sh = s0 >> 1;

    unsigned long long a01[4], a23[4];

    // ---- layer 1: [32,390] x [390,128] ----
    #pragma unroll
    for (int f = 0; f < 4; f++) { a01[f] = 0ull; a23[f] = 0ull; }
    {
        const float4* wp = (const float4*)W1 + fg;
        for (int cb = 0; cb < 388; cb += 4) {
            int cb4 = cb >> 2;
            int colA = (((sh + cb4) & 15) << 1);
            int colB = (((sh + 1 + cb4) & 15) << 1);
            #pragma unroll
            for (int u = 0; u < 4; u++)
                gemm_step(xs, wp, cb + u, colA, colB, a01, a23);
        }
        {   // remainder c = 388, 389 (same c>>2 = 97 group)
            int colA = (((sh + 97) & 15) << 1);
            int colB = (((sh + 1 + 97) & 15) << 1);
            gemm_step(xs, wp, 388, colA, colB, a01, a23);
            gemm_step(xs, wp, 389, colA, colB, a01, a23);
        }
        gemm_epilogue(h1, b1, fg, sh, a01, a23);
    }
    __syncthreads();

    // ---- layer 2: [32,128] x [128,128] ----
    #pragma unroll
    for (int f = 0; f < 4; f++) { a01[f] = 0ull; a23[f] = 0ull; }
    {
        const float4* wp = (const float4*)W2 + fg;
        for (int cb = 0; cb < FC; cb += 4) {
            int cb4 = cb >> 2;
            int colA = (((sh + cb4) & 15) << 1);
            int colB = (((sh + 1 + cb4) & 15) << 1);
            #pragma unroll
            for (int u = 0; u < 4; u++)
                gemm_step(h1, wp, cb + u, colA, colB, a01, a23);
        }
        gemm_epilogue(h2, b2, fg, sh, a01, a23);
    }
    __syncthreads();

    // ---- layer 3: [32,128] x [128,3] + sigmoid ----
    if (tid < 96) {
        const int s = tid / 3;
        const int o = tid - 3 * s;
        float sum = b3s[o];
        #pragma unroll 8
        for (int g = 0; g < FC; g++) {
            float hv = h2[g * 32 + XCOL(g, s)];
            sum = fmaf(hv, w3s[g * 3 + o], sum);
        }
        g_rgb[(base + s) * 3 + o] = 1.0f / (1.0f + expf(-sum));
    }
}

// ---------------------------------------------------------------------------
// Per-ray composite (unchanged math, better SM spread: 128 blocks of 32)
// ---------------------------------------------------------------------------
__global__ void __launch_bounds__(32) reduce_kernel(
    const float* __restrict__ sf,
    const float* __restrict__ dd,
    float* __restrict__ out)
{
    const int r = blockIdx.x * blockDim.x + threadIdx.x;
    if (r >= NRAYS) return;

    const float* s  = sf + (size_t)r * NS;
    const float* d  = dd + (size_t)r * NS;
    const float* rb = g_rgb + (size_t)r * NS * 3;

    float T = 1.0f, o0 = 0.0f, o1 = 0.0f, o2 = 0.0f;
    #pragma unroll 4
    for (int i = 0; i < NS; i++) {
        float x = s[i] - 10.0f;
        float sig = log1pf(expf(x));
        float alpha = (i == NS - 1) ? 1.0f
                    : (1.0f - expf(-sig * d[i] * 25.0f));
        float w = alpha * T;
        o0 = fmaf(w, rb[i * 3 + 0], o0);
        o1 = fmaf(w, rb[i * 3 + 1], o1);
        o2 = fmaf(w, rb[i * 3 + 2], o2);
        T *= (1.0f - alpha + 1e-10f);
    }
    out[r * 3 + 0] = o0;
    out[r * 3 + 1] = o1;
    out[r * 3 + 2] = o2;
}

// ---------------------------------------------------------------------------
extern "C" void kernel_launch(void* const* d_in, const int* in_sizes, int n_in,
                              void* d_out, int out_size)
{
    const float* sigma = (const float*)d_in[0];
    const float* app   = (const float*)d_in[1];
    const float* view  = (const float*)d_in[2];
    const float* dists = (const float*)d_in[3];
    const float* W1    = (const float*)d_in[4];
    const float* b1    = (const float*)d_in[5];
    const float* W2    = (const float*)d_in[6];
    const float* b2    = (const float*)d_in[7];
    const float* W3    = (const float*)d_in[8];
    const float* b3    = (const float*)d_in[9];
    float* out = (float*)d_out;

    const int smem_bytes = (392 * 32 + 128 * 32 + 128 * 32 + 384 + 4) * 4;
    cudaFuncSetAttribute(mlp_kernel,
                         cudaFuncAttributeMaxDynamicSharedMemorySize, smem_bytes);

    mlp_kernel<<<NSAMP / STILE, THREADS, smem_bytes>>>(
        app, view, W1, b1, W2, b2, W3, b3);
    reduce_kernel<<<NRAYS / 32, 32>>>(sigma, dists, out);
}